// round 6
// baseline (speedup 1.0000x reference)
#include <cuda_runtime.h>
#include <math_constants.h>

#define B_   8
#define N_   4096
#define F_   64
#define P_   1024
#define K_   16
#define CPF_ 32
#define CF_  96      // CPF + F
#define C_   128
#define DM_  2
#define KK_  256     // K*K
#define EPS_ 0.001f

// Scratch for kNN indices (allocation-free rule: __device__ global)
__device__ int g_idx[B_ * P_ * K_];

// ---------------------------------------------------------------------------
// kNN: warp per query. Warp-distributed sorted top-32 (lane l = rank l).
// Candidates filtered vs current rank-31, inserted via ballot + shfl_up shift.
// Total order: lexicographic (d2, index) -> matches jax.lax.top_k + [::2].
// d2 arithmetic mirrors XLA: dot = k-ordered FMA chain; norms = square+reduce
// (no FMA); d2 = (|q|^2 - 2*dot) + |p|^2.
// Also writes the qrs passthrough (out[0 : B*P*3)) during point staging.
// ---------------------------------------------------------------------------
__global__ void knn_kernel(const float* __restrict__ pts, float* __restrict__ out) {
    extern __shared__ float4 sp[];   // 4096 x (x, y, z, |p|^2) = 64 KB

    const int batch = blockIdx.x >> 7;      // 128 blocks per batch
    const int warp  = threadIdx.x >> 5;     // 8 warps = 8 queries / block
    const int lane  = threadIdx.x & 31;

    const float* bp = pts + batch * N_ * 3;
    for (int i = threadIdx.x; i < N_; i += blockDim.x) {
        float x = bp[i * 3 + 0], y = bp[i * 3 + 1], z = bp[i * 3 + 2];
        // |p|^2 matches jnp.sum(p*p, -1): rounded squares, reduce in order, no FMA
        float pn = __fadd_rn(__fadd_rn(__fmul_rn(x, x), __fmul_rn(y, y)), __fmul_rn(z, z));
        sp[i] = make_float4(x, y, z, pn);
    }
    // qrs passthrough: each block covers 8 queries x 3 floats = 24 elements
    {
        int base = ((blockIdx.x & 127) << 3) * 3;            // within-batch float offset
        if (threadIdx.x < 24)
            out[batch * P_ * 3 + base + threadIdx.x] = bp[base + threadIdx.x];
    }
    __syncthreads();

    const int p = ((blockIdx.x & 127) << 3) + warp;   // query index 0..1023
    const float4 q = sp[p];                            // qrs = pts[:, :P]

    float ld = CUDART_INF_F;     // this lane's list element (rank = lane)
    int   li = 0x7fffffff;
    const unsigned FULL = 0xffffffffu;

    #pragma unroll 1
    for (int r = 0; r < N_ / 32; r++) {
        int n = (r << 5) + lane;
        float4 c = sp[n];
        // einsum dot: FMA-accumulated over k = 0,1,2 (XLA/gemm order)
        float dot = __fmaf_rn(q.z, c.z, __fmaf_rn(q.y, c.y, __fmul_rn(q.x, c.x)));
        // d2 = (qn - 2*dot) + pn  (reference association; 2*dot exact)
        float d2 = __fadd_rn(__fsub_rn(q.w, __fmul_rn(2.0f, dot)), c.w);

        float wd = __shfl_sync(FULL, ld, 31);
        int   wi = __shfl_sync(FULL, li, 31);
        bool pass = (d2 < wd) || (d2 == wd && n < wi);
        unsigned mask = __ballot_sync(FULL, pass);
        while (mask) {
            int src = __ffs(mask) - 1;
            mask &= mask - 1;
            float dn = __shfl_sync(FULL, d2, src);
            int   in = __shfl_sync(FULL, n, src);
            // elements strictly after the new one
            bool gt = (ld > dn) || (ld == dn && li > in);
            unsigned gb = __ballot_sync(FULL, gt);
            float pd = __shfl_up_sync(FULL, ld, 1);
            int   pi = __shfl_up_sync(FULL, li, 1);
            if (gb) {                       // else: worse than all 32, drop
                int pos = __ffs(gb) - 1;
                if (lane > pos)      { ld = pd; li = pi; }
                else if (lane == pos){ ld = dn; li = in; }
            }
        }
    }
    // dilation D=2: keep even ranks 0,2,...,30
    if (!(lane & 1))
        g_idx[(batch * P_ + p) * K_ + (lane >> 1)] = li;
}

// ---------------------------------------------------------------------------
// Per-point fused MLP chain. One block (128 threads) per point.
// ---------------------------------------------------------------------------
__device__ __forceinline__ float elu_f(float x) {
    return x > 0.0f ? x : expm1f(x);
}
__device__ __forceinline__ float bn_f(const float* __restrict__ bnp, int ch, int c, float x) {
    float g = __ldg(bnp + c);
    float b = __ldg(bnp + ch + c);
    float m = __ldg(bnp + 2 * ch + c);
    float v = __ldg(bnp + 3 * ch + c);
    // correctly-rounded 1/sqrt, matching jax.lax.rsqrt; immune to fast-math
    float rs = __fdiv_rn(1.0f, __fsqrt_rn(v + EPS_));
    return (x - m) * g * rs + b;
}

__global__ __launch_bounds__(128) void point_kernel(
    const float* __restrict__ pts,    const float* __restrict__ features,
    const float* __restrict__ w_fts0, const float* __restrict__ bn_fts0,
    const float* __restrict__ w_fts1, const float* __restrict__ bn_fts1,
    const float* __restrict__ w_x0,   const float* __restrict__ bn_x0,
    const float* __restrict__ w_x1,   const float* __restrict__ bn_x1,
    const float* __restrict__ w_x2,   const float* __restrict__ bn_x2,
    const float* __restrict__ w_dw,   const float* __restrict__ w_pw,
    const float* __restrict__ bn_sep, float* __restrict__ out)
{
    __shared__ float s_local[K_ * 3];        // 48
    __shared__ float s_nnin[K_][CF_];        // 16 x 96, cols [0:32)=f, [32:96)=features
    __shared__ float s_h0[K_][CPF_];         // 16 x 32
    __shared__ float s_xa[KK_];              // 256
    __shared__ float s_xb[KK_];              // 256
    __shared__ float s_fx[K_][CF_];          // 16 x 96
    __shared__ float s_t[CF_ * DM_];         // 192
    __shared__ int   s_idx[K_];

    const int tid = threadIdx.x;
    const int bp  = blockIdx.x;              // b*1024 + p
    const int b   = bp >> 10;
    const int p   = bp & 1023;

    if (tid < K_) s_idx[tid] = g_idx[bp * K_ + tid];
    __syncthreads();

    const float* bpts = pts + b * N_ * 3;
    if (tid < 48) {
        int k = tid / 3, c = tid - 3 * k;
        s_local[tid] = bpts[s_idx[k] * 3 + c] - bpts[p * 3 + c];
    }
    const float* bft = features + b * N_ * F_;
    for (int e = tid; e < K_ * F_; e += 128) {
        int k = e >> 6, f = e & 63;
        s_nnin[k][CPF_ + f] = bft[s_idx[k] * F_ + f];
    }
    __syncthreads();

    // stage A: h0 = bn0(elu(local @ w_fts0))       (16 x 32)
    for (int e = tid; e < K_ * CPF_; e += 128) {
        int k = e >> 5, j = e & 31;
        float a = s_local[k * 3 + 0] * __ldg(w_fts0 + 0 * CPF_ + j)
                + s_local[k * 3 + 1] * __ldg(w_fts0 + 1 * CPF_ + j)
                + s_local[k * 3 + 2] * __ldg(w_fts0 + 2 * CPF_ + j);
        s_h0[k][j] = bn_f(bn_fts0, CPF_, j, elu_f(a));
    }
    __syncthreads();

    // stage B: f = bn1(elu(h0 @ w_fts1)) -> nn_in[:, 0:32]
    for (int e = tid; e < K_ * CPF_; e += 128) {
        int k = e >> 5, j = e & 31;
        float a = 0.0f;
        #pragma unroll
        for (int j0 = 0; j0 < CPF_; j0++)
            a += s_h0[k][j0] * __ldg(w_fts1 + j0 * CPF_ + j);
        s_nnin[k][j] = bn_f(bn_fts1, CPF_, j, elu_f(a));
    }

    // stage C: x0[o] = bn_x0(elu(sum_{kc<48} local[kc] * w_x0[kc][o]))
    // (independent of stage B's writes; barrier comes after)
    for (int e = tid; e < KK_; e += 128) {
        float a = 0.0f;
        #pragma unroll
        for (int kc = 0; kc < 48; kc++)
            a += s_local[kc] * __ldg(w_x0 + kc * KK_ + e);
        s_xa[e] = bn_f(bn_x0, KK_, e, elu_f(a));
    }
    __syncthreads();

    // stage D: x1[c][m] = bn_x1(elu(sum_k x0[k][c] * w_x1[k][c][m])), flat idx c*16+m
    for (int e = tid; e < KK_; e += 128) {
        int c = e >> 4, m = e & 15;
        float a = 0.0f;
        #pragma unroll
        for (int k = 0; k < 16; k++)
            a += s_xa[k * 16 + c] * __ldg(w_x1 + (k * 16 + c) * 16 + m);
        s_xb[e] = bn_f(bn_x1, KK_, e, elu_f(a));
    }
    __syncthreads();

    // stage E: x2[c][m] = bn_x2(sum_k x1[k][c] * w_x2[k][c][m])  (no elu)
    for (int e = tid; e < KK_; e += 128) {
        int c = e >> 4, m = e & 15;
        float a = 0.0f;
        #pragma unroll
        for (int k = 0; k < 16; k++)
            a += s_xb[k * 16 + c] * __ldg(w_x2 + (k * 16 + c) * 16 + m);
        s_xa[e] = bn_f(bn_x2, KK_, e, a);
    }
    __syncthreads();

    // stage F: fts_X[i][f] = sum_j x2[i][j] * nn_in[j][f]   (16 x 96)
    for (int e = tid; e < K_ * CF_; e += 128) {
        int i = e / CF_, f = e - i * CF_;
        float a = 0.0f;
        #pragma unroll
        for (int j = 0; j < 16; j++)
            a += s_xa[i * 16 + j] * s_nnin[j][f];
        s_fx[i][f] = a;
    }
    __syncthreads();

    // stage G: t[c][m] = sum_k fts_X[k][c] * w_dw[k][c][m]   (96 x 2)
    for (int e = tid; e < CF_ * DM_; e += 128) {
        int c = e >> 1, m = e & 1;
        float a = 0.0f;
        #pragma unroll
        for (int k = 0; k < 16; k++)
            a += s_fx[k][c] * __ldg(w_dw + (k * CF_ + c) * DM_ + m);
        s_t[e] = a;
    }
    __syncthreads();

    // stage H: out[o] = bn_sep(elu(sum_i t[i] * w_pw[i][o]))   (128)
    {
        int o = tid;
        float a = 0.0f;
        #pragma unroll 8
        for (int i = 0; i < CF_ * DM_; i++)
            a += s_t[i] * __ldg(w_pw + i * C_ + o);
        out[B_ * P_ * 3 + bp * C_ + o] = bn_f(bn_sep, C_, o, elu_f(a));
    }
}

// ---------------------------------------------------------------------------
extern "C" void kernel_launch(void* const* d_in, const int* in_sizes, int n_in,
                              void* d_out, int out_size) {
    const float* pts      = (const float*)d_in[0];
    const float* features = (const float*)d_in[1];
    const float* w_fts0   = (const float*)d_in[2];
    const float* bn_fts0  = (const float*)d_in[3];
    const float* w_fts1   = (const float*)d_in[4];
    const float* bn_fts1  = (const float*)d_in[5];
    const float* w_x0     = (const float*)d_in[6];
    const float* bn_x0    = (const float*)d_in[7];
    const float* w_x1     = (const float*)d_in[8];
    const float* bn_x1    = (const float*)d_in[9];
    const float* w_x2     = (const float*)d_in[10];
    const float* bn_x2    = (const float*)d_in[11];
    const float* w_dw     = (const float*)d_in[12];
    const float* w_pw     = (const float*)d_in[13];
    const float* bn_sep   = (const float*)d_in[14];
    float* out = (float*)d_out;

    // kNN (+ qrs passthrough): 64KB dynamic smem (opt-in above 48KB).
    cudaFuncSetAttribute(knn_kernel, cudaFuncAttributeMaxDynamicSharedMemorySize, 65536);
    knn_kernel<<<B_ * 128, 256, 65536>>>(pts, out);

    // fused per-point chain
    point_kernel<<<B_ * P_, 128>>>(pts, features,
                                   w_fts0, bn_fts0, w_fts1, bn_fts1,
                                   w_x0, bn_x0, w_x1, bn_x1, w_x2, bn_x2,
                                   w_dw, w_pw, bn_sep, out);
}